// round 8
// baseline (speedup 1.0000x reference)
#include <cuda_runtime.h>
#include <cuda_bf16.h>

// Problem constants
#define NF 8
#define V 12
#define D 64
#define BATCH 131072
#define NPAIR 28                       // C(8,2)
#define GRAM_ELEMS (NPAIR * V * V)     // 4032 floats = 16128 B

#define GRAM_DOTS 4032
#define TOTAL_DOTS (GRAM_DOTS + NF * V)   // 4128 dot-units

#define THREADS 512
#define NBLK 128                       // <= 148 SMs -> single wave, co-resident
#define EPT 2                          // 128 * 512 * 2 = 131072 = BATCH
#define UNITS_PER_BLK 40               // 128*40 = 5120 >= 4128; 40 % 8 == 0 keeps
                                       // all unit-boundaries warp-uniform
#define ACTIVE_A (UNITS_PER_BLK * 4)   // 160 threads (5 whole warps) do phase A

// Device globals (no allocation allowed)
__device__ float    g_gram[GRAM_ELEMS];  // [pair][i][j] = dot(emb[f][i], emb[g][j])
__device__ float4   g_pf[NF * V];        // (.x=dot(e,a0), .y=dot(e,a1), .z=first, .w=0)
__device__ float    g_partial[NBLK];     // per-block weighted-loss partials
__device__ unsigned g_arrive;            // grid barrier counter (reset by last block)
__device__ unsigned g_done;              // last-block counter (self-wrapping atomicInc)

__device__ __forceinline__ float dot4(float4 a, float4 b) {
    return a.x * b.x + a.y * b.y + a.z * b.z + a.w * b.w;
}

__global__ void __launch_bounds__(THREADS)
fm_fused_kernel(const float* __restrict__ emb,
                const float* __restrict__ emb_first,
                const float* __restrict__ a_emb,
                const float* __restrict__ action_first,
                const int*   __restrict__ feats,
                const float* __restrict__ label,
                const float* __restrict__ pos_weights,
                float* __restrict__ out)
{
    __shared__ float  s_gram[GRAM_ELEMS];
    __shared__ float4 s_pf[NF * V];
    __shared__ float  s_wsum[THREADS / 32];
    __shared__ int    s_is_last;

    const int tid = threadIdx.x;

    // ----------------------------------------------------------------------
    // Phase A: this block's slice of the gram/PF precompute.
    // Each 64-dot is split over 4 threads (same-warp groups). All warps that
    // enter execute shuffles uniformly: validity and the gram/PF split are
    // 8-unit (= one warp of 8 units) aligned, and invalid threads clamp their
    // unit to 0 but still execute the shuffles; only stores are predicated.
    // ----------------------------------------------------------------------
    if (tid < ACTIVE_A) {
        int unit  = blockIdx.x * UNITS_PER_BLK + (tid >> 2);
        int part  = tid & 3;
        bool valid = (unit < TOTAL_DOTS);
        int u = valid ? unit : 0;      // whole warp is invalid together -> uniform

        if (u < GRAM_DOTS) {
            int p = u / (V * V);
            int r = u - p * (V * V);
            int i = r / V, j = r - (r / V) * V;
            // decode pair p -> (f, g), f < g, order (0,1),(0,2),...,(6,7)
            int f = 0, g = 1, c = p;
            #pragma unroll
            for (int ff = 0; ff < NF - 1; ++ff) {
                int cnt = NF - 1 - ff;
                if (c < cnt) { f = ff; g = ff + 1 + c; break; }
                c -= cnt;
            }
            const float4* ra = (const float4*)(emb + (size_t)(f * V + i) * D) + part * 4;
            const float4* rb = (const float4*)(emb + (size_t)(g * V + j) * D) + part * 4;
            float4 a0 = __ldg(&ra[0]), b0 = __ldg(&rb[0]);
            float4 a1 = __ldg(&ra[1]), b1 = __ldg(&rb[1]);
            float4 a2 = __ldg(&ra[2]), b2 = __ldg(&rb[2]);
            float4 a3 = __ldg(&ra[3]), b3 = __ldg(&rb[3]);
            float s = (dot4(a0, b0) + dot4(a2, b2)) + (dot4(a1, b1) + dot4(a3, b3));
            s += __shfl_xor_sync(0xffffffffu, s, 1);
            s += __shfl_xor_sync(0xffffffffu, s, 2);
            if (valid && part == 0) g_gram[u] = s;
        } else {
            int t = u - GRAM_DOTS;      // 0..95 = f*V + i
            const float4* rr = (const float4*)(emb + (size_t)t * D) + part * 4;
            const float4* a0 = (const float4*)(a_emb) + part * 4;
            const float4* a1 = (const float4*)(a_emb + D) + part * 4;
            float s0 = 0.f, s1 = 0.f;
            #pragma unroll
            for (int q = 0; q < 4; ++q) {
                float4 e = __ldg(&rr[q]);
                float4 x = __ldg(&a0[q]);
                float4 y = __ldg(&a1[q]);
                s0 += dot4(e, x);
                s1 += dot4(e, y);
            }
            s0 += __shfl_xor_sync(0xffffffffu, s0, 1);
            s0 += __shfl_xor_sync(0xffffffffu, s0, 2);
            s1 += __shfl_xor_sync(0xffffffffu, s1, 1);
            s1 += __shfl_xor_sync(0xffffffffu, s1, 2);
            if (valid && part == 0) g_pf[t] = make_float4(s0, s1, __ldg(&emb_first[t]), 0.f);
        }
        __threadfence();               // publish gram/pf writes to GPU scope
    }

    // ----------------------------------------------------------------------
    // Prefetch main-phase inputs into registers; these DRAM loads overlap the
    // grid barrier wait below.
    // ----------------------------------------------------------------------
    int   idx[EPT][NF];
    float2 lab[EPT], pw[EPT];
    #pragma unroll
    for (int e = 0; e < EPT; ++e) {
        int b = blockIdx.x * (THREADS * EPT) + e * THREADS + tid;
        #pragma unroll
        for (int f = 0; f < NF; ++f)
            idx[e][f] = __ldg(&feats[f * BATCH + b]);
        lab[e] = __ldg(((const float2*)label) + b);
        pw[e]  = __ldg(((const float2*)pos_weights) + b);
    }
    const float af0 = __ldg(&action_first[0]);
    const float af1 = __ldg(&action_first[1]);

    // ----------------------------------------------------------------------
    // Grid barrier: all NBLK blocks are co-resident (NBLK <= #SMs, 1 wave),
    // so spinning is safe. g_arrive is reset to 0 by the last-finishing block
    // at the end of every launch (stream-ordered before the next replay).
    // ----------------------------------------------------------------------
    __syncthreads();                   // all phase-A fences in this block done
    if (tid == 0) {
        atomicAdd(&g_arrive, 1u);
        while (atomicAdd(&g_arrive, 0u) < NBLK) __nanosleep(64);
    }
    __syncthreads();
    __threadfence();                   // acquire: see all blocks' gram/pf writes

    // ----------------------------------------------------------------------
    // Stage tables into smem (served from hot L2; L1 has no stale copy since
    // it is flushed at launch and these addresses were untouched this launch).
    // ----------------------------------------------------------------------
    {
        const float4* src = (const float4*)g_gram;
        float4* dst = (float4*)s_gram;
        for (int k = tid; k < GRAM_ELEMS / 4; k += THREADS) dst[k] = src[k];
        if (tid < NF * V) s_pf[tid] = g_pf[tid];
    }
    __syncthreads();

    // ----------------------------------------------------------------------
    // Main phase: 2 elements per thread.
    // ----------------------------------------------------------------------
    float lsum = 0.f;
    #pragma unroll
    for (int e = 0; e < EPT; ++e) {
        int b = blockIdx.x * (THREADS * EPT) + e * THREADS + tid;

        float d0 = 0.f, d1 = 0.f, fo = 0.f;
        #pragma unroll
        for (int f = 0; f < NF; ++f) {
            float4 pf = s_pf[f * V + idx[e][f]];
            d0 += pf.x; d1 += pf.y; fo += pf.z;
        }

        float pair = 0.f;
        int p = 0;
        #pragma unroll
        for (int f = 0; f < NF; ++f) {
            int base_f = idx[e][f] * V;
            #pragma unroll
            for (int g = f + 1; g < NF; ++g) {
                pair += s_gram[p * (V * V) + base_f + idx[e][g]];
                ++p;
            }
        }

        float inf0 = d0 + fo + af0;
        float inf1 = d1 + fo + af1;
        float e0 = inf0 - lab[e].x;
        float e1 = inf1 - lab[e].y;
        lsum += pw[e].x * e0 * e0 + pw[e].y * e1 * e1;

        // Outputs: inferences [B,2] at [0,2B), loss at 2B, pair [B,1] after it
        ((float2*)out)[b] = make_float2(inf0, inf1);
        out[2 * BATCH + 1 + b] = pair;
    }

    // Block reduction of weighted loss (all shuffles full-warp)
    #pragma unroll
    for (int o = 16; o > 0; o >>= 1) lsum += __shfl_xor_sync(0xffffffffu, lsum, o);
    if ((tid & 31) == 0) s_wsum[tid >> 5] = lsum;
    __syncthreads();
    if (tid < 32) {
        float v = (tid < THREADS / 32) ? s_wsum[tid] : 0.f;
        #pragma unroll
        for (int o = 16; o > 0; o >>= 1) v += __shfl_xor_sync(0xffffffffu, v, o);
        if (tid == 0) {
            g_partial[blockIdx.x] = v;
            __threadfence();
            // wraps to 0 after NBLK increments -> self-resetting across replays
            unsigned old = atomicInc(&g_done, NBLK - 1);
            s_is_last = (old == NBLK - 1);
        }
    }
    __syncthreads();

    // Last-finishing block: reduce the NBLK partials, write mean loss,
    // reset the grid-barrier counter for the next replay.
    if (s_is_last) {
        __threadfence();
        float v = (tid < NBLK) ? g_partial[tid] : 0.f;
        #pragma unroll
        for (int o = 16; o > 0; o >>= 1) v += __shfl_xor_sync(0xffffffffu, v, o);
        if ((tid & 31) == 0) s_wsum[tid >> 5] = v;
        __syncthreads();
        if (tid < 32) {
            float w = (tid < THREADS / 32) ? s_wsum[tid] : 0.f;
            #pragma unroll
            for (int o = 16; o > 0; o >>= 1) w += __shfl_xor_sync(0xffffffffu, w, o);
            if (tid == 0) {
                out[2 * BATCH] = w * (1.0f / (float)BATCH);
                atomicExch(&g_arrive, 0u);   // reset grid barrier for next launch
            }
        }
    }
}

// ---------------------------------------------------------------------------
// Launch. Inputs (metadata order):
//   0 emb_tables (8,12,64) f32   1 emb_first (8,12,1) f32
//   2 action_emb (2,64) f32      3 action_first (2,1) f32
//   4 label (B,2) f32            5 pos_weights (B,2) f32
//   6 feats (8,B) i32
// Output: [inferences (B,2) | loss (1) | pair (B,1)] f32
// ---------------------------------------------------------------------------
extern "C" void kernel_launch(void* const* d_in, const int* in_sizes, int n_in,
                              void* d_out, int out_size)
{
    const float* emb_tables   = (const float*)d_in[0];
    const float* emb_first    = (const float*)d_in[1];
    const float* action_emb   = (const float*)d_in[2];
    const float* action_first = (const float*)d_in[3];
    const float* label        = (const float*)d_in[4];
    const float* pos_weights  = (const float*)d_in[5];
    const int*   feats        = (const int*)d_in[6];
    float* out = (float*)d_out;

    fm_fused_kernel<<<NBLK, THREADS>>>(emb_tables, emb_first, action_emb,
                                       action_first, feats, label, pos_weights, out);
}